// round 8
// baseline (speedup 1.0000x reference)
#include <cuda_runtime.h>
#include <cuda_bf16.h>
#include <math.h>
#include <stdint.h>

using bf16 = __nv_bfloat16;

#define NB   32
#define SR   2048
#define SP   2048
#define DIN  400
#define HID  512
#define KPAD 448            // DIN padded to multiple of 64

// ---------------- scratch (device globals; no runtime alloc) ----------------
__device__ bf16  g_q [(size_t)NB*SR*HID];
__device__ bf16  g_k [(size_t)NB*SP*HID];
__device__ bf16  g_v [(size_t)NB*SP*HID];
__device__ bf16  g_o [(size_t)NB*SR*HID];
__device__ float g_x [(size_t)NB*SR*DIN];
__device__ bf16  g_ar[(size_t)NB*SR*KPAD];      // rgb  bf16, K-padded
__device__ bf16  g_ap[(size_t)NB*SP*KPAD];      // pose bf16, K-padded
__device__ bf16  g_wq[(size_t)HID*KPAD];        // W^T bf16 [n][k]
__device__ bf16  g_wk[(size_t)HID*KPAD];
__device__ bf16  g_wv[(size_t)HID*KPAD];
__device__ bf16  g_wp[(size_t)KPAD*HID];        // Wp^T bf16 [n(448)][k(512)]

// ---------------- PTX helpers ----------------
__device__ __forceinline__ void mma16816(float c[4], const uint32_t a[4], const uint32_t b0, const uint32_t b1) {
    asm volatile(
        "mma.sync.aligned.m16n8k16.row.col.f32.bf16.bf16.f32 "
        "{%0,%1,%2,%3}, {%4,%5,%6,%7}, {%8,%9}, {%0,%1,%2,%3};\n"
        : "+f"(c[0]), "+f"(c[1]), "+f"(c[2]), "+f"(c[3])
        : "r"(a[0]), "r"(a[1]), "r"(a[2]), "r"(a[3]), "r"(b0), "r"(b1));
}
__device__ __forceinline__ void ldsm_x4(uint32_t r[4], const void* p) {
    uint32_t addr = (uint32_t)__cvta_generic_to_shared(p);
    asm volatile("ldmatrix.sync.aligned.m8n8.x4.shared.b16 {%0,%1,%2,%3}, [%4];"
                 : "=r"(r[0]), "=r"(r[1]), "=r"(r[2]), "=r"(r[3]) : "r"(addr));
}
__device__ __forceinline__ void ldsm_x4t(uint32_t r[4], const void* p) {
    uint32_t addr = (uint32_t)__cvta_generic_to_shared(p);
    asm volatile("ldmatrix.sync.aligned.m8n8.x4.trans.shared.b16 {%0,%1,%2,%3}, [%4];"
                 : "=r"(r[0]), "=r"(r[1]), "=r"(r[2]), "=r"(r[3]) : "r"(addr));
}
__device__ __forceinline__ void cpa16(void* s, const void* g) {
    uint32_t addr = (uint32_t)__cvta_generic_to_shared(s);
    asm volatile("cp.async.cg.shared.global [%0], [%1], 16;" :: "r"(addr), "l"(g));
}
#define CP_COMMIT() asm volatile("cp.async.commit_group;")
__device__ __forceinline__ void cp_wait0() { asm volatile("cp.async.wait_group 0;"); }
__device__ __forceinline__ void cp_wait1() { asm volatile("cp.async.wait_group 1;"); }

// ---------------- conversion kernels ----------------
__global__ __launch_bounds__(256) void cvt_act(const float* __restrict__ in, bf16* __restrict__ out, int rows) {
    const int total = rows * (KPAD / 8);
    for (int id = blockIdx.x * 256 + threadIdx.x; id < total; id += gridDim.x * 256) {
        const int row = id / (KPAD / 8), c8 = id % (KPAD / 8);
        __align__(16) bf16 h[8];
        if (c8 < DIN / 8) {
            float4 f0 = *(const float4*)(in + (size_t)row * DIN + 8 * c8);
            float4 f1 = *(const float4*)(in + (size_t)row * DIN + 8 * c8 + 4);
            h[0] = __float2bfloat16(f0.x); h[1] = __float2bfloat16(f0.y);
            h[2] = __float2bfloat16(f0.z); h[3] = __float2bfloat16(f0.w);
            h[4] = __float2bfloat16(f1.x); h[5] = __float2bfloat16(f1.y);
            h[6] = __float2bfloat16(f1.z); h[7] = __float2bfloat16(f1.w);
        } else {
            #pragma unroll
            for (int i = 0; i < 8; i++) h[i] = __float2bfloat16(0.f);
        }
        *(uint4*)(out + (size_t)row * KPAD + 8 * c8) = *(const uint4*)h;
    }
}
__global__ __launch_bounds__(256) void cvt_w_all(
    const float* __restrict__ Wq, const float* __restrict__ Wk,
    const float* __restrict__ Wv, const float* __restrict__ Wp,
    bf16* __restrict__ oq, bf16* __restrict__ ok,
    bf16* __restrict__ ov, bf16* __restrict__ op)
{
    const int id = blockIdx.x * 256 + threadIdx.x;
    const int mat = blockIdx.y;
    if (mat < 3) {
        if (id >= HID * KPAD) return;
        const float* in = mat == 0 ? Wq : (mat == 1 ? Wk : Wv);
        bf16* out = mat == 0 ? oq : (mat == 1 ? ok : ov);
        const int col = id % KPAD, row = id / KPAD;
        out[(size_t)row * KPAD + col] = __float2bfloat16(col < DIN ? in[(size_t)col * HID + row] : 0.f);
    } else {
        if (id >= KPAD * HID) return;
        const int col = id % HID, row = id / HID;
        op[(size_t)row * HID + col] = __float2bfloat16(row < DIN ? Wp[(size_t)col * DIN + row] : 0.f);
    }
}

// ---------------- pipelined bf16 GEMM v3: 3-stage, occ-2 ----------------
#define G_ASZ 9216
#define G_BSZ 4608
#define G_STG 13824
template<int MODE>
__global__ __launch_bounds__(256, 2) void gemm3_kernel(
    const bf16* __restrict__ A, int ld, int nk,
    const bf16* __restrict__ B, const float* __restrict__ bias,
    const float* __restrict__ R, const float* __restrict__ gatep,
    void* __restrict__ outp, int Nout, int ldout)
{
    extern __shared__ __align__(16) bf16 sm2[];

    const int tid  = threadIdx.x;
    const int warp = tid >> 5, lane = tid & 31;
    const int wm = warp >> 1, wn = warp & 1;
    const int m0 = blockIdx.y * 128, n0 = blockIdx.x * 64;

    const int a_row  = lane & 15;
    const int a_col8 = (lane >> 4) * 8;
    const int b_nrow = (lane & 7) + ((lane >> 4) << 3);
    const int b_koff = lane & 8;

    float c[2][4][4];
    #pragma unroll
    for (int i = 0; i < 2; i++)
        #pragma unroll
        for (int j = 0; j < 4; j++)
            #pragma unroll
            for (int t = 0; t < 4; t++) c[i][j][t] = 0.f;

    auto load_stage = [&](int ks, int buf) {
        bf16* sA = sm2 + buf * G_STG;
        bf16* sB = sA + G_ASZ;
        const bf16* Asrc = A + (size_t)m0 * ld + ks * 64;
        #pragma unroll
        for (int i = 0; i < 4; i++) {
            const int id = tid + 256 * i;
            const int r = id >> 3, c8 = id & 7;
            cpa16(&sA[r * 72 + 8 * c8], Asrc + (size_t)r * ld + 8 * c8);
        }
        const bf16* Bsrc = B + (size_t)n0 * ld + ks * 64;
        #pragma unroll
        for (int i = 0; i < 2; i++) {
            const int id = tid + 256 * i;
            const int r = id >> 3, c8 = id & 7;
            cpa16(&sB[r * 72 + 8 * c8], Bsrc + (size_t)r * ld + 8 * c8);
        }
        CP_COMMIT();
    };

    load_stage(0, 0);
    if (nk > 1) load_stage(1, 1);
    int buf = 0;
    for (int t = 0; t < nk; t++) {
        if (t + 1 < nk) cp_wait1(); else cp_wait0();
        __syncthreads();
        if (t + 2 < nk) load_stage(t + 2, (buf + 2) % 3);

        const bf16* As_ = sm2 + buf * G_STG;
        const bf16* Bs_ = As_ + G_ASZ;
        #pragma unroll
        for (int kk = 0; kk < 4; kk++) {
            uint32_t a[2][4];
            #pragma unroll
            for (int mi = 0; mi < 2; mi++)
                ldsm_x4(a[mi], &As_[(wm * 32 + mi * 16 + a_row) * 72 + kk * 16 + a_col8]);
            #pragma unroll
            for (int ng = 0; ng < 2; ng++) {
                uint32_t bb[4];
                ldsm_x4(bb, &Bs_[(wn * 32 + ng * 16 + b_nrow) * 72 + kk * 16 + b_koff]);
                #pragma unroll
                for (int mi = 0; mi < 2; mi++) {
                    mma16816(c[mi][ng * 2 + 0], a[mi], bb[0], bb[1]);
                    mma16816(c[mi][ng * 2 + 1], a[mi], bb[2], bb[3]);
                }
            }
        }
        __syncthreads();
        buf = (buf + 1) % 3;
    }

    float gate = 0.f;
    if (MODE == 1) gate = *gatep;
    #pragma unroll
    for (int mi = 0; mi < 2; mi++) {
        const int r = m0 + wm * 32 + mi * 16 + (lane >> 2);
        #pragma unroll
        for (int nj = 0; nj < 4; nj++) {
            const int cn = n0 + wn * 32 + nj * 8 + 2 * (lane & 3);
            if (cn < Nout) {
                const float b0 = bias[cn], b1 = bias[cn + 1];
                const float v0 = c[mi][nj][0] + b0, v1 = c[mi][nj][1] + b1;
                const float v2 = c[mi][nj][2] + b0, v3 = c[mi][nj][3] + b1;
                if (MODE == 0) {
                    bf16* out = (bf16*)outp;
                    __nv_bfloat162 p0; p0.x = __float2bfloat16(v0); p0.y = __float2bfloat16(v1);
                    __nv_bfloat162 p1; p1.x = __float2bfloat16(v2); p1.y = __float2bfloat16(v3);
                    *(__nv_bfloat162*)&out[(size_t)r * ldout + cn]       = p0;
                    *(__nv_bfloat162*)&out[(size_t)(r + 8) * ldout + cn] = p1;
                } else {
                    float* out = (float*)outp;
                    const size_t i0 = (size_t)r * ldout + cn;
                    const size_t i1 = (size_t)(r + 8) * ldout + cn;
                    out[i0]     = R[i0]     + gate * v0;
                    out[i0 + 1] = R[i0 + 1] + gate * v1;
                    out[i1]     = R[i1]     + gate * v2;
                    out[i1 + 1] = R[i1 + 1] + gate * v3;
                }
            }
        }
    }
}

// ---------------- attention v4: 512 threads / 16 warps ----------------
#define QSTR 520
#define PSTR 72
#define A_QS 0
#define A_KS 33280
#define A_VS 66560
#define A_PS 99840
#define A_L_BYTES 208896
#define SMEM_ATTN 209152
#define ATHREADS 512

__global__ __launch_bounds__(ATHREADS, 1) void attn_kernel()
{
    extern __shared__ __align__(16) char sm[];
    bf16*  Qs = (bf16*)sm + A_QS;
    bf16*  Ks = (bf16*)sm + A_KS;
    bf16*  Vs = (bf16*)sm + A_VS;
    bf16*  Ps = (bf16*)sm + A_PS;
    float* l  = (float*)(sm + A_L_BYTES);

    const int tid = threadIdx.x, warp = tid >> 5, lane = tid & 31;
    const int b = blockIdx.y, q0 = blockIdx.x * 64;
    const bf16* Qg = g_q + ((size_t)b * SR + q0) * HID;
    const bf16* Kg = g_k + (size_t)b * SP * HID;
    const bf16* Vg = g_v + (size_t)b * SP * HID;

    auto load64x512 = [&](bf16* dst, const bf16* src) {
        #pragma unroll
        for (int i = 0; i < 8; i++) {
            const int id = tid + ATHREADS * i;
            const int r = id >> 6, c8 = id & 63;
            cpa16(&dst[r * QSTR + 8 * c8], src + (size_t)r * HID + 8 * c8);
        }
        CP_COMMIT();
    };

    load64x512(Qs, Qg);
    load64x512(Ks, Kg);
    load64x512(Vs, Vg);
    if (tid < 64) l[tid] = 0.f;

    const int wmS = warp >> 2, wnS = warp & 3;   // 4x4 warp grid: 16q x 16k per warp
    const float scale = 0.044194173824159216f;   // 1/sqrt(512)

    const int a_row  = lane & 15;
    const int a_col8 = (lane >> 4) * 8;
    const int b_nrow = (lane & 7) + ((lane >> 4) << 3);
    const int b_koff = lane & 8;

    float of[4][4][4];                           // PV: warp owns h cols [warp*32, +32)
    #pragma unroll
    for (int i = 0; i < 4; i++)
        #pragma unroll
        for (int j = 0; j < 4; j++)
            #pragma unroll
            for (int t = 0; t < 4; t++) of[i][j][t] = 0.f;

    float rs0 = 0.f, rs1 = 0.f;

    for (int kt = 0; kt < 32; kt++) {
        if (kt < 31) cp_wait1(); else cp_wait0();
        __syncthreads();

        // ---- S = Q K^T : 16x16 per warp over 512 h ----
        float sc[2][4];
        #pragma unroll
        for (int j = 0; j < 2; j++)
            #pragma unroll
            for (int t = 0; t < 4; t++) sc[j][t] = 0.f;

        #pragma unroll 8
        for (int ks = 0; ks < 32; ks++) {
            uint32_t a[4];
            ldsm_x4(a, &Qs[(wmS * 16 + a_row) * QSTR + ks * 16 + a_col8]);
            uint32_t bb[4];
            ldsm_x4(bb, &Ks[(wnS * 16 + b_nrow) * QSTR + ks * 16 + b_koff]);
            mma16816(sc[0], a, bb[0], bb[1]);
            mma16816(sc[1], a, bb[2], bb[3]);
        }
        __syncthreads();

        if (kt < 31) load64x512(Ks, Kg + (size_t)(kt + 1) * 64 * HID);

        // ---- softmax numerator (no max subtraction; logits O(1)) ----
        {
            const int r0 = wmS * 16 + (lane >> 2);
            #pragma unroll
            for (int nj = 0; nj < 2; nj++) {
                const int n = wnS * 16 + nj * 8 + 2 * (lane & 3);
                const float e00 = __expf(sc[nj][0] * scale);
                const float e01 = __expf(sc[nj][1] * scale);
                const float e10 = __expf(sc[nj][2] * scale);
                const float e11 = __expf(sc[nj][3] * scale);
                rs0 += e00 + e01; rs1 += e10 + e11;
                __nv_bfloat162 p0; p0.x = __float2bfloat16(e00); p0.y = __float2bfloat16(e01);
                __nv_bfloat162 p1; p1.x = __float2bfloat16(e10); p1.y = __float2bfloat16(e11);
                *(__nv_bfloat162*)&Ps[ r0      * PSTR + n] = p0;
                *(__nv_bfloat162*)&Ps[(r0 + 8) * PSTR + n] = p1;
            }
        }

        if (kt < 31) cp_wait1(); else cp_wait0();
        __syncthreads();

        // ---- O += P V ; warp owns h cols [warp*32, +32) ----
        #pragma unroll
        for (int kk2 = 0; kk2 < 4; kk2++) {
            uint32_t bb[2][4];
            #pragma unroll
            for (int ng = 0; ng < 2; ng++)
                ldsm_x4t(bb[ng], &Vs[(kk2 * 16 + a_row) * QSTR + warp * 32 + ng * 16 + a_col8]);
            #pragma unroll
            for (int mi = 0; mi < 4; mi++) {
                uint32_t a[4];
                ldsm_x4(a, &Ps[(mi * 16 + a_row) * PSTR + kk2 * 16 + a_col8]);
                #pragma unroll
                for (int ng = 0; ng < 2; ng++) {
                    mma16816(of[mi][ng * 2 + 0], a, bb[ng][0], bb[ng][1]);
                    mma16816(of[mi][ng * 2 + 1], a, bb[ng][2], bb[ng][3]);
                }
            }
        }
        __syncthreads();

        if (kt < 31) load64x512(Vs, Vg + (size_t)(kt + 1) * 64 * HID);
    }

    // ---- denominators: 4 warps per row-group contribute via atomics ----
    {
        float s0 = rs0, s1 = rs1;
        s0 += __shfl_xor_sync(0xffffffffu, s0, 1);
        s0 += __shfl_xor_sync(0xffffffffu, s0, 2);
        s1 += __shfl_xor_sync(0xffffffffu, s1, 1);
        s1 += __shfl_xor_sync(0xffffffffu, s1, 2);
        if ((lane & 3) == 0) {
            atomicAdd(&l[wmS * 16 + (lane >> 2)],     s0);
            atomicAdd(&l[wmS * 16 + (lane >> 2) + 8], s1);
        }
    }
    __syncthreads();

    // ---- normalize + store O ----
    #pragma unroll
    for (int mi = 0; mi < 4; mi++) {
        const int r = mi * 16 + (lane >> 2);
        const float inv0 = 1.f / l[r];
        const float inv1 = 1.f / l[r + 8];
        #pragma unroll
        for (int nj = 0; nj < 4; nj++) {
            const int h = warp * 32 + nj * 8 + 2 * (lane & 3);
            const size_t base = ((size_t)b * SR + q0 + r) * HID + h;
            __nv_bfloat162 p0, p1;
            p0.x = __float2bfloat16(of[mi][nj][0] * inv0);
            p0.y = __float2bfloat16(of[mi][nj][1] * inv0);
            p1.x = __float2bfloat16(of[mi][nj][2] * inv1);
            p1.y = __float2bfloat16(of[mi][nj][3] * inv1);
            *(__nv_bfloat162*)&g_o[base]           = p0;
            *(__nv_bfloat162*)&g_o[base + 8 * HID] = p1;
        }
    }
}

// ---------------- LayerNorm over 400 dims (one warp per row) ----------------
__global__ __launch_bounds__(256) void ln_kernel(
    const float* __restrict__ x, const float* __restrict__ gamma,
    const float* __restrict__ beta, float* __restrict__ out)
{
    const int warp = threadIdx.x >> 5, lane = threadIdx.x & 31;
    const size_t row = (size_t)blockIdx.x * 8 + warp;
    const float* xr = x + row * DIN;
    float v[13], s = 0.f, s2 = 0.f;
    #pragma unroll
    for (int i = 0; i < 13; i++) {
        const int idx = lane + 32 * i;
        float val = (idx < DIN) ? xr[idx] : 0.f;
        v[i] = val; s += val; s2 += val * val;
    }
    #pragma unroll
    for (int off = 16; off; off >>= 1) {
        s  += __shfl_xor_sync(0xffffffffu, s,  off);
        s2 += __shfl_xor_sync(0xffffffffu, s2, off);
    }
    const float mu   = s * (1.f / DIN);
    const float var  = s2 * (1.f / DIN) - mu * mu;
    const float rstd = rsqrtf(var + 1e-5f);
    float* orow = out + row * DIN;
    #pragma unroll
    for (int i = 0; i < 13; i++) {
        const int idx = lane + 32 * i;
        if (idx < DIN) orow[idx] = (v[i] - mu) * rstd * gamma[idx] + beta[idx];
    }
}

// ---------------- launch ----------------
extern "C" void kernel_launch(void* const* d_in, const int* in_sizes, int n_in,
                              void* d_out, int out_size)
{
    const float* rgb   = (const float*)d_in[0];
    const float* pose  = (const float*)d_in[1];
    const float* Wq    = (const float*)d_in[2];
    const float* bq    = (const float*)d_in[3];
    const float* Wk    = (const float*)d_in[4];
    const float* bk    = (const float*)d_in[5];
    const float* Wv    = (const float*)d_in[6];
    const float* bv    = (const float*)d_in[7];
    const float* Wp    = (const float*)d_in[8];
    const float* bp    = (const float*)d_in[9];
    const float* gamma = (const float*)d_in[10];
    const float* beta  = (const float*)d_in[11];
    const float* gate  = (const float*)d_in[12];

    void *pq, *pk, *pv, *po, *px, *par, *pap, *pwq, *pwk, *pwv, *pwp;
    cudaGetSymbolAddress(&pq,  g_q);
    cudaGetSymbolAddress(&pk,  g_k);
    cudaGetSymbolAddress(&pv,  g_v);
    cudaGetSymbolAddress(&po,  g_o);
    cudaGetSymbolAddress(&px,  g_x);
    cudaGetSymbolAddress(&par, g_ar);
    cudaGetSymbolAddress(&pap, g_ap);
    cudaGetSymbolAddress(&pwq, g_wq);
    cudaGetSymbolAddress(&pwk, g_wk);
    cudaGetSymbolAddress(&pwv, g_wv);
    cudaGetSymbolAddress(&pwp, g_wp);

    const int M = NB * SR;    // 65536

    // --- conversions ---
    cvt_act<<<2048, 256>>>(rgb,  (bf16*)par, M);
    cvt_act<<<2048, 256>>>(pose, (bf16*)pap, M);
    cvt_w_all<<<dim3((HID*KPAD + 255)/256, 4), 256>>>(Wq, Wk, Wv, Wp,
        (bf16*)pwq, (bf16*)pwk, (bf16*)pwv, (bf16*)pwp);

    // --- GEMMs ---
    const int smem3 = 3 * G_STG * 2;
    cudaFuncSetAttribute(gemm3_kernel<0>, cudaFuncAttributeMaxDynamicSharedMemorySize, smem3);
    cudaFuncSetAttribute(gemm3_kernel<1>, cudaFuncAttributeMaxDynamicSharedMemorySize, smem3);

    dim3 blk(256);
    dim3 gq(HID / 64, M / 128);
    gemm3_kernel<0><<<gq, blk, smem3>>>((const bf16*)par, KPAD, KPAD/64,
        (const bf16*)pwq, bq, nullptr, nullptr, pq, HID, HID);
    gemm3_kernel<0><<<gq, blk, smem3>>>((const bf16*)pap, KPAD, KPAD/64,
        (const bf16*)pwk, bk, nullptr, nullptr, pk, HID, HID);
    gemm3_kernel<0><<<gq, blk, smem3>>>((const bf16*)pap, KPAD, KPAD/64,
        (const bf16*)pwv, bv, nullptr, nullptr, pv, HID, HID);

    // --- attention ---
    cudaFuncSetAttribute(attn_kernel, cudaFuncAttributeMaxDynamicSharedMemorySize, SMEM_ATTN);
    attn_kernel<<<dim3(SR / 64, NB), ATHREADS, SMEM_ATTN>>>();

    // --- projection + gated residual ---
    dim3 gp(KPAD / 64, M / 128);
    gemm3_kernel<1><<<gp, blk, smem3>>>((const bf16*)po, HID, HID/64,
        (const bf16*)pwp, bp, rgb, gate, px, DIN, DIN);

    // --- layernorm ---
    ln_kernel<<<M / 8, blk>>>((const float*)px, gamma, beta, (float*)d_out);
}

// round 9
// speedup vs baseline: 1.1230x; 1.1230x over previous
#include <cuda_runtime.h>
#include <cuda_bf16.h>
#include <math.h>
#include <stdint.h>

using bf16 = __nv_bfloat16;

#define NB   32
#define SR   2048
#define SP   2048
#define DIN  400
#define HID  512
#define KPAD 448            // DIN padded to multiple of 64

// ---------------- scratch (device globals; no runtime alloc) ----------------
__device__ bf16  g_q [(size_t)NB*SR*HID];
__device__ bf16  g_k [(size_t)NB*SP*HID];
__device__ bf16  g_v [(size_t)NB*SP*HID];
__device__ bf16  g_o [(size_t)NB*SR*HID];
__device__ float g_x [(size_t)NB*SR*DIN];
__device__ bf16  g_ar[(size_t)NB*SR*KPAD];      // rgb  bf16, K-padded
__device__ bf16  g_ap[(size_t)NB*SP*KPAD];      // pose bf16, K-padded
__device__ bf16  g_wq[(size_t)HID*KPAD];        // W^T bf16 [n(512)][k(448)]
__device__ bf16  g_wk[(size_t)HID*KPAD];
__device__ bf16  g_wv[(size_t)HID*KPAD];
__device__ bf16  g_wp[(size_t)HID*HID];         // Wp^T bf16 [n(512, zero>=400)][k(512)]

// ---------------- PTX helpers ----------------
__device__ __forceinline__ void mma16816(float c[4], const uint32_t a[4], const uint32_t b0, const uint32_t b1) {
    asm volatile(
        "mma.sync.aligned.m16n8k16.row.col.f32.bf16.bf16.f32 "
        "{%0,%1,%2,%3}, {%4,%5,%6,%7}, {%8,%9}, {%0,%1,%2,%3};\n"
        : "+f"(c[0]), "+f"(c[1]), "+f"(c[2]), "+f"(c[3])
        : "r"(a[0]), "r"(a[1]), "r"(a[2]), "r"(a[3]), "r"(b0), "r"(b1));
}
__device__ __forceinline__ void ldsm_x4(uint32_t r[4], const void* p) {
    uint32_t addr = (uint32_t)__cvta_generic_to_shared(p);
    asm volatile("ldmatrix.sync.aligned.m8n8.x4.shared.b16 {%0,%1,%2,%3}, [%4];"
                 : "=r"(r[0]), "=r"(r[1]), "=r"(r[2]), "=r"(r[3]) : "r"(addr));
}
__device__ __forceinline__ void ldsm_x4t(uint32_t r[4], const void* p) {
    uint32_t addr = (uint32_t)__cvta_generic_to_shared(p);
    asm volatile("ldmatrix.sync.aligned.m8n8.x4.trans.shared.b16 {%0,%1,%2,%3}, [%4];"
                 : "=r"(r[0]), "=r"(r[1]), "=r"(r[2]), "=r"(r[3]) : "r"(addr));
}
__device__ __forceinline__ void cpa16(void* s, const void* g) {
    uint32_t addr = (uint32_t)__cvta_generic_to_shared(s);
    asm volatile("cp.async.cg.shared.global [%0], [%1], 16;" :: "r"(addr), "l"(g));
}
#define CP_COMMIT() asm volatile("cp.async.commit_group;")
__device__ __forceinline__ void cp_wait0() { asm volatile("cp.async.wait_group 0;"); }
__device__ __forceinline__ void cp_wait1() { asm volatile("cp.async.wait_group 1;"); }

// ---------------- conversion kernels ----------------
__global__ __launch_bounds__(256) void cvt_act(const float* __restrict__ in, bf16* __restrict__ out, int rows) {
    const int total = rows * (KPAD / 8);
    for (int id = blockIdx.x * 256 + threadIdx.x; id < total; id += gridDim.x * 256) {
        const int row = id / (KPAD / 8), c8 = id % (KPAD / 8);
        __align__(16) bf16 h[8];
        if (c8 < DIN / 8) {
            float4 f0 = *(const float4*)(in + (size_t)row * DIN + 8 * c8);
            float4 f1 = *(const float4*)(in + (size_t)row * DIN + 8 * c8 + 4);
            h[0] = __float2bfloat16(f0.x); h[1] = __float2bfloat16(f0.y);
            h[2] = __float2bfloat16(f0.z); h[3] = __float2bfloat16(f0.w);
            h[4] = __float2bfloat16(f1.x); h[5] = __float2bfloat16(f1.y);
            h[6] = __float2bfloat16(f1.z); h[7] = __float2bfloat16(f1.w);
        } else {
            #pragma unroll
            for (int i = 0; i < 8; i++) h[i] = __float2bfloat16(0.f);
        }
        *(uint4*)(out + (size_t)row * KPAD + 8 * c8) = *(const uint4*)h;
    }
}
// y<3: W[400][512] -> Wt[512][448]   y=3: Wp[512][400] -> Wpt[512][512] (rows>=400 zero)
__global__ __launch_bounds__(256) void cvt_w_all(
    const float* __restrict__ Wq, const float* __restrict__ Wk,
    const float* __restrict__ Wv, const float* __restrict__ Wp,
    bf16* __restrict__ oq, bf16* __restrict__ ok,
    bf16* __restrict__ ov, bf16* __restrict__ op)
{
    const int id = blockIdx.x * 256 + threadIdx.x;
    const int mat = blockIdx.y;
    if (mat < 3) {
        if (id >= HID * KPAD) return;
        const float* in = mat == 0 ? Wq : (mat == 1 ? Wk : Wv);
        bf16* out = mat == 0 ? oq : (mat == 1 ? ok : ov);
        const int col = id % KPAD, row = id / KPAD;
        out[(size_t)row * KPAD + col] = __float2bfloat16(col < DIN ? in[(size_t)col * HID + row] : 0.f);
    } else {
        if (id >= HID * HID) return;
        const int col = id % HID, row = id / HID;
        op[(size_t)row * HID + col] = __float2bfloat16(row < DIN ? Wp[(size_t)col * DIN + row] : 0.f);
    }
}

// ---------------- GEMM v4: BM128 x BN128 x BK64, 2-stage, occ-2 ----------------
// C[M,N] = A[M][k] * Bt[n][k]^T (+bias). MODE 0: bf16 out. MODE 1: fp32 R + gate*C.
#define G4_ASZ 9216      // 128*72 halves
#define G4_BSZ 9216      // 128*72 halves
#define G4_STG 18432     // per-stage halves (36 KB)
template<int MODE>
__global__ __launch_bounds__(256, 2) void gemm4_kernel(
    const bf16* __restrict__ A, int ld, int nk,
    const bf16* __restrict__ B, const float* __restrict__ bias,
    const float* __restrict__ R, const float* __restrict__ gatep,
    void* __restrict__ outp, int Nout, int ldout)
{
    extern __shared__ __align__(16) bf16 sm2[];   // [2][G4_STG]

    const int tid  = threadIdx.x;
    const int warp = tid >> 5, lane = tid & 31;
    const int wm = warp >> 1, wn = warp & 1;      // warp tile: 32 m x 64 n
    const int m0 = blockIdx.y * 128, n0 = blockIdx.x * 128;

    const int a_row  = lane & 15;
    const int a_col8 = (lane >> 4) * 8;
    const int b_nrow = (lane & 7) + ((lane >> 4) << 3);
    const int b_koff = lane & 8;

    float c[2][8][4];
    #pragma unroll
    for (int i = 0; i < 2; i++)
        #pragma unroll
        for (int j = 0; j < 8; j++)
            #pragma unroll
            for (int t = 0; t < 4; t++) c[i][j][t] = 0.f;

    auto load_stage = [&](int ks, int buf) {
        bf16* sA = sm2 + buf * G4_STG;
        bf16* sB = sA + G4_ASZ;
        const bf16* Asrc = A + (size_t)m0 * ld + ks * 64;
        #pragma unroll
        for (int i = 0; i < 4; i++) {
            const int id = tid + 256 * i;
            const int r = id >> 3, c8 = id & 7;
            cpa16(&sA[r * 72 + 8 * c8], Asrc + (size_t)r * ld + 8 * c8);
        }
        const bf16* Bsrc = B + (size_t)n0 * ld + ks * 64;
        #pragma unroll
        for (int i = 0; i < 4; i++) {
            const int id = tid + 256 * i;
            const int r = id >> 3, c8 = id & 7;
            cpa16(&sB[r * 72 + 8 * c8], Bsrc + (size_t)r * ld + 8 * c8);
        }
        CP_COMMIT();
    };

    load_stage(0, 0);
    for (int t = 0; t < nk; t++) {
        if (t + 1 < nk) { load_stage(t + 1, (t + 1) & 1); cp_wait1(); }
        else cp_wait0();
        __syncthreads();

        const bf16* As_ = sm2 + (t & 1) * G4_STG;
        const bf16* Bs_ = As_ + G4_ASZ;
        #pragma unroll
        for (int kk = 0; kk < 4; kk++) {
            uint32_t a[2][4];
            #pragma unroll
            for (int mi = 0; mi < 2; mi++)
                ldsm_x4(a[mi], &As_[(wm * 32 + mi * 16 + a_row) * 72 + kk * 16 + a_col8]);
            #pragma unroll
            for (int ng = 0; ng < 4; ng++) {
                uint32_t bb[4];
                ldsm_x4(bb, &Bs_[(wn * 64 + ng * 16 + b_nrow) * 72 + kk * 16 + b_koff]);
                #pragma unroll
                for (int mi = 0; mi < 2; mi++) {
                    mma16816(c[mi][ng * 2 + 0], a[mi], bb[0], bb[1]);
                    mma16816(c[mi][ng * 2 + 1], a[mi], bb[2], bb[3]);
                }
            }
        }
        __syncthreads();
    }

    float gate = 0.f;
    if (MODE == 1) gate = *gatep;
    #pragma unroll
    for (int mi = 0; mi < 2; mi++) {
        const int r = m0 + wm * 32 + mi * 16 + (lane >> 2);
        #pragma unroll
        for (int nj = 0; nj < 8; nj++) {
            const int cn = n0 + wn * 64 + nj * 8 + 2 * (lane & 3);
            if (cn < Nout) {
                const float b0 = bias[cn], b1 = bias[cn + 1];
                const float v0 = c[mi][nj][0] + b0, v1 = c[mi][nj][1] + b1;
                const float v2 = c[mi][nj][2] + b0, v3 = c[mi][nj][3] + b1;
                if (MODE == 0) {
                    bf16* out = (bf16*)outp;
                    __nv_bfloat162 p0; p0.x = __float2bfloat16(v0); p0.y = __float2bfloat16(v1);
                    __nv_bfloat162 p1; p1.x = __float2bfloat16(v2); p1.y = __float2bfloat16(v3);
                    *(__nv_bfloat162*)&out[(size_t)r * ldout + cn]       = p0;
                    *(__nv_bfloat162*)&out[(size_t)(r + 8) * ldout + cn] = p1;
                } else {
                    float* out = (float*)outp;
                    const size_t i0 = (size_t)r * ldout + cn;
                    const size_t i1 = (size_t)(r + 8) * ldout + cn;
                    out[i0]     = R[i0]     + gate * v0;
                    out[i0 + 1] = R[i0 + 1] + gate * v1;
                    out[i1]     = R[i1]     + gate * v2;
                    out[i1 + 1] = R[i1 + 1] + gate * v3;
                }
            }
        }
    }
}

// ---------------- attention (R6 winner): 256 threads, single-buffer interleaved cp.async ----------------
#define QSTR 520
#define PSTR 72
#define A_QS 0
#define A_KS 33280
#define A_VS 66560
#define A_PS 99840
#define A_L_BYTES 208896
#define SMEM_ATTN 209152

__global__ __launch_bounds__(256, 1) void attn_kernel()
{
    extern __shared__ __align__(16) char sm[];
    bf16*  Qs = (bf16*)sm + A_QS;
    bf16*  Ks = (bf16*)sm + A_KS;
    bf16*  Vs = (bf16*)sm + A_VS;
    bf16*  Ps = (bf16*)sm + A_PS;
    float* l  = (float*)(sm + A_L_BYTES);

    const int tid = threadIdx.x, warp = tid >> 5, lane = tid & 31;
    const int b = blockIdx.y, q0 = blockIdx.x * 64;
    const bf16* Qg = g_q + ((size_t)b * SR + q0) * HID;
    const bf16* Kg = g_k + (size_t)b * SP * HID;
    const bf16* Vg = g_v + (size_t)b * SP * HID;

    auto load64x512 = [&](bf16* dst, const bf16* src) {
        #pragma unroll
        for (int i = 0; i < 16; i++) {
            const int id = tid + 256 * i;
            const int r = id >> 6, c8 = id & 63;
            cpa16(&dst[r * QSTR + 8 * c8], src + (size_t)r * HID + 8 * c8);
        }
        CP_COMMIT();
    };

    load64x512(Qs, Qg);
    load64x512(Ks, Kg);
    load64x512(Vs, Vg);
    if (tid < 64) l[tid] = 0.f;

    const int wmS = warp >> 1, wnS = warp & 1;
    const float scale = 0.044194173824159216f;

    const int a_row  = lane & 15;
    const int a_col8 = (lane >> 4) * 8;
    const int b_nrow = (lane & 7) + ((lane >> 4) << 3);
    const int b_koff = lane & 8;

    float of[4][8][4];
    #pragma unroll
    for (int i = 0; i < 4; i++)
        #pragma unroll
        for (int j = 0; j < 8; j++)
            #pragma unroll
            for (int t = 0; t < 4; t++) of[i][j][t] = 0.f;

    float rs0 = 0.f, rs1 = 0.f;

    for (int kt = 0; kt < 32; kt++) {
        if (kt < 31) cp_wait1(); else cp_wait0();
        __syncthreads();

        float sc[4][4];
        #pragma unroll
        for (int j = 0; j < 4; j++)
            #pragma unroll
            for (int t = 0; t < 4; t++) sc[j][t] = 0.f;

        #pragma unroll 8
        for (int ks = 0; ks < 32; ks++) {
            uint32_t a[4];
            ldsm_x4(a, &Qs[(wmS * 16 + a_row) * QSTR + ks * 16 + a_col8]);
            #pragma unroll
            for (int ng = 0; ng < 2; ng++) {
                uint32_t bb[4];
                ldsm_x4(bb, &Ks[(wnS * 32 + ng * 16 + b_nrow) * QSTR + ks * 16 + b_koff]);
                mma16816(sc[ng * 2 + 0], a, bb[0], bb[1]);
                mma16816(sc[ng * 2 + 1], a, bb[2], bb[3]);
            }
        }
        __syncthreads();

        if (kt < 31) load64x512(Ks, Kg + (size_t)(kt + 1) * 64 * HID);

        {
            const int r0 = wmS * 16 + (lane >> 2);
            #pragma unroll
            for (int nj = 0; nj < 4; nj++) {
                const int n = wnS * 32 + nj * 8 + 2 * (lane & 3);
                const float e00 = __expf(sc[nj][0] * scale);
                const float e01 = __expf(sc[nj][1] * scale);
                const float e10 = __expf(sc[nj][2] * scale);
                const float e11 = __expf(sc[nj][3] * scale);
                rs0 += e00 + e01; rs1 += e10 + e11;
                __nv_bfloat162 p0; p0.x = __float2bfloat16(e00); p0.y = __float2bfloat16(e01);
                __nv_bfloat162 p1; p1.x = __float2bfloat16(e10); p1.y = __float2bfloat16(e11);
                *(__nv_bfloat162*)&Ps[ r0      * PSTR + n] = p0;
                *(__nv_bfloat162*)&Ps[(r0 + 8) * PSTR + n] = p1;
            }
        }

        if (kt < 31) cp_wait1(); else cp_wait0();
        __syncthreads();

        #pragma unroll
        for (int kk2 = 0; kk2 < 4; kk2++) {
            uint32_t bb[4][4];
            #pragma unroll
            for (int ng = 0; ng < 4; ng++)
                ldsm_x4t(bb[ng], &Vs[(kk2 * 16 + a_row) * QSTR + warp * 64 + ng * 16 + a_col8]);
            #pragma unroll
            for (int mi = 0; mi < 4; mi++) {
                uint32_t a[4];
                ldsm_x4(a, &Ps[(mi * 16 + a_row) * PSTR + kk2 * 16 + a_col8]);
                #pragma unroll
                for (int ng = 0; ng < 4; ng++) {
                    mma16816(of[mi][ng * 2 + 0], a, bb[ng][0], bb[ng][1]);
                    mma16816(of[mi][ng * 2 + 1], a, bb[ng][2], bb[ng][3]);
                }
            }
        }
        __syncthreads();

        if (kt < 31) load64x512(Vs, Vg + (size_t)(kt + 1) * 64 * HID);
    }

    {
        float s0 = rs0, s1 = rs1;
        s0 += __shfl_xor_sync(0xffffffffu, s0, 1);
        s0 += __shfl_xor_sync(0xffffffffu, s0, 2);
        s1 += __shfl_xor_sync(0xffffffffu, s1, 1);
        s1 += __shfl_xor_sync(0xffffffffu, s1, 2);
        if ((lane & 3) == 0) {
            atomicAdd(&l[wmS * 16 + (lane >> 2)],     s0);
            atomicAdd(&l[wmS * 16 + (lane >> 2) + 8], s1);
        }
    }
    __syncthreads();

    #pragma unroll
    for (int mi = 0; mi < 4; mi++) {
        const int r = mi * 16 + (lane >> 2);
        const float inv0 = 1.f / l[r];
        const float inv1 = 1.f / l[r + 8];
        #pragma unroll
        for (int nj = 0; nj < 8; nj++) {
            const int h = warp * 64 + nj * 8 + 2 * (lane & 3);
            const size_t base = ((size_t)b * SR + q0 + r) * HID + h;
            __nv_bfloat162 p0, p1;
            p0.x = __float2bfloat16(of[mi][nj][0] * inv0);
            p0.y = __float2bfloat16(of[mi][nj][1] * inv0);
            p1.x = __float2bfloat16(of[mi][nj][2] * inv1);
            p1.y = __float2bfloat16(of[mi][nj][3] * inv1);
            *(__nv_bfloat162*)&g_o[base]           = p0;
            *(__nv_bfloat162*)&g_o[base + 8 * HID] = p1;
        }
    }
}

// ---------------- LayerNorm over 400 dims (one warp per row) ----------------
__global__ __launch_bounds__(256) void ln_kernel(
    const float* __restrict__ x, const float* __restrict__ gamma,
    const float* __restrict__ beta, float* __restrict__ out)
{
    const int warp = threadIdx.x >> 5, lane = threadIdx.x & 31;
    const size_t row = (size_t)blockIdx.x * 8 + warp;
    const float* xr = x + row * DIN;
    float v[13], s = 0.f, s2 = 0.f;
    #pragma unroll
    for (int i = 0; i < 13; i++) {
        const int idx = lane + 32 * i;
        float val = (idx < DIN) ? xr[idx] : 0.f;
        v[i] = val; s += val; s2 += val * val;
    }
    #pragma unroll
    for (int off = 16; off; off >>= 1) {
        s  += __shfl_xor_sync(0xffffffffu, s,  off);
        s2 += __shfl_xor_sync(0xffffffffu, s2, off);
    }
    const float mu   = s * (1.f / DIN);
    const float var  = s2 * (1.f / DIN) - mu * mu;
    const float rstd = rsqrtf(var + 1e-5f);
    float* orow = out + row * DIN;
    #pragma unroll
    for (int i = 0; i < 13; i++) {
        const int idx = lane + 32 * i;
        if (idx < DIN) orow[idx] = (v[i] - mu) * rstd * gamma[idx] + beta[idx];
    }
}

// ---------------- launch ----------------
extern "C" void kernel_launch(void* const* d_in, const int* in_sizes, int n_in,
                              void* d_out, int out_size)
{
    const float* rgb   = (const float*)d_in[0];
    const float* pose  = (const float*)d_in[1];
    const float* Wq    = (const float*)d_in[2];
    const float* bq    = (const float*)d_in[3];
    const float* Wk    = (const float*)d_in[4];
    const float* bk    = (const float*)d_in[5];
    const float* Wv    = (const float*)d_in[6];
    const float* bv    = (const float*)d_in[7];
    const float* Wp    = (const float*)d_in[8];
    const float* bp    = (const float*)d_in[9];
    const float* gamma = (const float*)d_in[10];
    const float* beta  = (const float*)d_in[11];
    const float* gate  = (const float*)d_in[12];

    void *pq, *pk, *pv, *po, *px, *par, *pap, *pwq, *pwk, *pwv, *pwp;
    cudaGetSymbolAddress(&pq,  g_q);
    cudaGetSymbolAddress(&pk,  g_k);
    cudaGetSymbolAddress(&pv,  g_v);
    cudaGetSymbolAddress(&po,  g_o);
    cudaGetSymbolAddress(&px,  g_x);
    cudaGetSymbolAddress(&par, g_ar);
    cudaGetSymbolAddress(&pap, g_ap);
    cudaGetSymbolAddress(&pwq, g_wq);
    cudaGetSymbolAddress(&pwk, g_wk);
    cudaGetSymbolAddress(&pwv, g_wv);
    cudaGetSymbolAddress(&pwp, g_wp);

    const int M = NB * SR;    // 65536

    // --- conversions ---
    cvt_act<<<2048, 256>>>(rgb,  (bf16*)par, M);
    cvt_act<<<2048, 256>>>(pose, (bf16*)pap, M);
    cvt_w_all<<<dim3((HID*HID + 255)/256, 4), 256>>>(Wq, Wk, Wv, Wp,
        (bf16*)pwq, (bf16*)pwk, (bf16*)pwv, (bf16*)pwp);

    // --- GEMMs: BN=128, 2-stage, occ 2 ---
    const int smem4 = 2 * G4_STG * 2;    // 73728 B
    cudaFuncSetAttribute(gemm4_kernel<0>, cudaFuncAttributeMaxDynamicSharedMemorySize, smem4);
    cudaFuncSetAttribute(gemm4_kernel<1>, cudaFuncAttributeMaxDynamicSharedMemorySize, smem4);

    dim3 blk(256);
    dim3 gq(HID / 128, M / 128);   // (4, 512)
    gemm4_kernel<0><<<gq, blk, smem4>>>((const bf16*)par, KPAD, KPAD/64,
        (const bf16*)pwq, bq, nullptr, nullptr, pq, HID, HID);
    gemm4_kernel<0><<<gq, blk, smem4>>>((const bf16*)pap, KPAD, KPAD/64,
        (const bf16*)pwk, bk, nullptr, nullptr, pk, HID, HID);
    gemm4_kernel<0><<<gq, blk, smem4>>>((const bf16*)pap, KPAD, KPAD/64,
        (const bf16*)pwv, bv, nullptr, nullptr, pv, HID, HID);

    // --- attention ---
    cudaFuncSetAttribute(attn_kernel, cudaFuncAttributeMaxDynamicSharedMemorySize, SMEM_ATTN);
    attn_kernel<<<dim3(SR / 64, NB), blk, SMEM_ATTN>>>();

    // --- projection + gated residual ---
    dim3 gp(HID / 128, M / 128);   // n tiles cover 512, stores predicated to 400
    gemm4_kernel<1><<<gp, blk, smem4>>>((const bf16*)po, HID, HID/64,
        (const bf16*)pwp, bp, rgb, gate, px, DIN, DIN);

    // --- layernorm ---
    ln_kernel<<<M / 8, blk>>>((const float*)px, gamma, beta, (float*)d_out);
}